// round 16
// baseline (speedup 1.0000x reference)
#include <cuda_runtime.h>
#include <cuda_fp16.h>
#include <math.h>
#include <stdint.h>

#define BATCH 8
#define SEQ   2048
#define DM    768

// GEMM tiling
#define BM 128
#define BN 128
#define BK 64                       // 64 fp16 = 128 bytes per smem row
#define NSTAGE 3
#define A_TILE_BYTES (BM * 128)
#define B_TILE_BYTES (BN * 128)
#define STAGE_BYTES  (A_TILE_BYTES + B_TILE_BYTES)       // 32768
#define SMEM_TOTAL   (NSTAGE * STAGE_BYTES)              // 98304 -> 2 CTAs/SM

#define EXP_SHIFT 8.0f              // fixed softmax shift (cancels in normalization)

// ---------------------------------------------------------------------------
// Static device scratch
// ---------------------------------------------------------------------------
__device__ __align__(128) __half g_Xh [16384 * DM];           // fp16 X
__device__ __align__(128) __half g_WqT[DM * DM];              // fp16 Wq^T [e][k]
__device__ __align__(128) __half g_WkT[DM * DM];              // fp16 Wk^T
__device__ __align__(128) __half g_WvT[DM * DM];              // fp16 Wv^T
__device__ __align__(128) __half g_Qh [16384 * DM];           // fp16 Q/sqrt(d)
__device__ __align__(128) __half g_Kh [16384 * DM];           // fp16 K
__device__ __align__(128) __half g_VT [(BATCH * DM) * SEQ];   // fp16 V^T [b*768+e][s]
__device__ __align__(128) __half g_Ph [16384 * SEQ];          // fp16 unnormalized exp(s-8)
__device__ __align__(128) float  g_Part[16384 * 16];          // per-CTA row-sum partials
__device__ __align__(128) float  g_Sum [16384];               // row sums

// ---------------------------------------------------------------------------
// PTX helpers (baseline sm_100 ISA: cp.async, ldmatrix, mma.sync)
// ---------------------------------------------------------------------------
__device__ __forceinline__ uint32_t smem_u32(const void* p) {
    uint32_t a;
    asm("{ .reg .u64 t; cvta.to.shared.u64 t, %1; cvt.u32.u64 %0, t; }" : "=r"(a) : "l"(p));
    return a;
}
#define CP_ASYNC16(dst, src) \
    asm volatile("cp.async.cg.shared.global [%0], [%1], 16;" :: "r"(dst), "l"(src))
#define CP_COMMIT() asm volatile("cp.async.commit_group;" ::: "memory")
#define CP_WAIT1()  asm volatile("cp.async.wait_group 1;" ::: "memory")

__device__ __forceinline__ void ldsm_x4(uint32_t& r0, uint32_t& r1, uint32_t& r2, uint32_t& r3, uint32_t addr) {
    asm volatile("ldmatrix.sync.aligned.m8n8.x4.shared.b16 {%0,%1,%2,%3}, [%4];"
        : "=r"(r0), "=r"(r1), "=r"(r2), "=r"(r3) : "r"(addr));
}
__device__ __forceinline__ void mma_fp16(float* d, const uint32_t* a, const uint32_t* b) {
    asm volatile("mma.sync.aligned.m16n8k16.row.col.f32.f16.f16.f32 "
        "{%0,%1,%2,%3}, {%4,%5,%6,%7}, {%8,%9}, {%0,%1,%2,%3};"
        : "+f"(d[0]), "+f"(d[1]), "+f"(d[2]), "+f"(d[3])
        : "r"(a[0]), "r"(a[1]), "r"(a[2]), "r"(a[3]), "r"(b[0]), "r"(b[1]));
}

// ---------------------------------------------------------------------------
// NT GEMM via fp16 mma.sync: C[M,N] = A[M,:] . B[N,:]^T over K = NC*64.
// Modes:
//  2: fp16 *alpha -> C (ld 768), smem-staged coalesced   [proj Q / proj K]
//  4: fp16 transposed store -> V_T(batch), smem-staged   [proj V]
//  5: __expf(s-8) -> fp16 Ph (ld 2048), smem-staged + row partials -> aux
//  6: fp32 * (1/aux[m]) -> C (ld 768)                    [PV, fused normalization]
// ---------------------------------------------------------------------------
template <int MODE>
__global__ void __launch_bounds__(256, 2) gemm_mma(
    const __half* __restrict__ A, const __half* __restrict__ Bm,
    void* __restrict__ Cout, float* __restrict__ aux,
    int NC, int ldA, int ldB, float alpha)
{
    extern __shared__ __align__(1024) char smem[];
    const uint32_t sb = smem_u32(smem);
    const int tid = threadIdx.x;
    const int wid = tid >> 5, lid = tid & 31;
    const int wm = wid & 3, wn = wid >> 2;           // warp grid 4(m) x 2(n)

    const int aRow = blockIdx.y * BM;
    const int bRow = blockIdx.x * BN;
    const __half* gA0 = A  + (size_t)aRow * ldA;
    const __half* gB0 = Bm + (size_t)bRow * ldB;

    const int lr = tid >> 3, lc = tid & 7;

    float acc[2][8][4];
#pragma unroll
    for (int mi = 0; mi < 2; mi++)
#pragma unroll
        for (int ni = 0; ni < 8; ni++)
#pragma unroll
            for (int j = 0; j < 4; j++) acc[mi][ni][j] = 0.0f;

#define ISSUE_STAGE(chunk, stage) do { \
    uint32_t _sA = sb + (stage) * STAGE_BYTES; \
    uint32_t _sB = _sA + A_TILE_BYTES; \
    const __half* _gA = gA0 + (size_t)(chunk) * BK; \
    const __half* _gB = gB0 + (size_t)(chunk) * BK; \
    _Pragma("unroll") \
    for (int _j = 0; _j < 4; _j++) { \
        int _r = lr + _j * 32, _c = lc; \
        uint32_t _d = _r * 128 + ((_c ^ (_r & 7)) * 16); \
        CP_ASYNC16(_sA + _d, _gA + (size_t)_r * ldA + _c * 8); \
        CP_ASYNC16(_sB + _d, _gB + (size_t)_r * ldB + _c * 8); \
    } } while (0)

    for (int s = 0; s < 2; s++) {
        if (s < NC) ISSUE_STAGE(s, s);
        CP_COMMIT();
    }

    const int a_row = wm * 32 + (lid & 15);
    const int a_cSel = (lid >> 4);
    const int b_row = wn * 64 + (lid & 7) + ((lid >> 4) & 1) * 8;
    const int b_cSel = (lid >> 3) & 1;

    int stg = 0, stg2 = 2;
    for (int i = 0; i < NC; i++) {
        CP_WAIT1();
        __syncthreads();
        if (i + 2 < NC) ISSUE_STAGE(i + 2, stg2);
        CP_COMMIT();

        const uint32_t aBase = sb + stg * STAGE_BYTES;
        const uint32_t bBase = aBase + A_TILE_BYTES;
        stg2 = stg;
        stg = (stg + 1 == NSTAGE) ? 0 : stg + 1;
#pragma unroll
        for (int kk = 0; kk < 4; kk++) {
            uint32_t a[2][4], b[8][2];
#pragma unroll
            for (int mi = 0; mi < 2; mi++) {
                int row = a_row + mi * 16;
                int c = kk * 2 + a_cSel;
                ldsm_x4(a[mi][0], a[mi][1], a[mi][2], a[mi][3],
                        aBase + row * 128 + ((c ^ (row & 7)) * 16));
            }
#pragma unroll
            for (int nt = 0; nt < 4; nt++) {
                int row = b_row + nt * 16;
                int c = kk * 2 + b_cSel;
                ldsm_x4(b[2 * nt][0], b[2 * nt][1], b[2 * nt + 1][0], b[2 * nt + 1][1],
                        bBase + row * 128 + ((c ^ (row & 7)) * 16));
            }
#pragma unroll
            for (int mi = 0; mi < 2; mi++)
#pragma unroll
                for (int ni = 0; ni < 8; ni++)
                    mma_fp16(acc[mi][ni], a[mi], b[ni]);
        }
    }

    // ---- epilogue ----
    const int g = lid >> 2, q = (lid & 3) * 2;

    if (MODE == 4) {
        // transposed tile [e_local][s_local] in smem, then coalesced store
        __syncthreads();
        __half* st = (__half*)smem;                        // [128][136]
#pragma unroll
        for (int mi = 0; mi < 2; mi++)
#pragma unroll
            for (int hf = 0; hf < 2; hf++) {
                const int sl = wm * 32 + mi * 16 + g + hf * 8;
#pragma unroll
                for (int ni = 0; ni < 8; ni++) {
                    const int el = wn * 64 + ni * 8 + q;
                    st[el * 136 + sl]       = __float2half(acc[mi][ni][hf * 2 + 0]);
                    st[(el + 1) * 136 + sl] = __float2half(acc[mi][ni][hf * 2 + 1]);
                }
            }
        __syncthreads();
        const int s0 = aRow;
        const int r = tid >> 1, hh = tid & 1;
        const int eg = blockIdx.x * BN + r;
        uint4* dst = (uint4*)((__half*)Cout + (size_t)eg * 2048 + s0 + hh * 64);
        const uint4* src = (const uint4*)(st + r * 136 + hh * 64);
#pragma unroll
        for (int j = 0; j < 8; j++) dst[j] = src[j];
    } else if (MODE == 5) {
        // __expf(s-8): stage fp16 tile in smem, coalesced store; partials -> aux
        __syncthreads();
        __half* st = (__half*)smem;                            // [128][136] fp16
        float* rs = (float*)(smem + 128 * 136 * 2);            // [128][8] fp32
        const int slot = wn * 4 + (lid & 3);
#pragma unroll
        for (int mi = 0; mi < 2; mi++)
#pragma unroll
            for (int hf = 0; hf < 2; hf++) {
                const int rl = wm * 32 + mi * 16 + g + hf * 8;
                float part = 0.0f;
#pragma unroll
                for (int ni = 0; ni < 8; ni++) {
                    const int cl = wn * 64 + ni * 8 + q;
                    float e0 = __expf(acc[mi][ni][hf * 2 + 0] - EXP_SHIFT);
                    float e1 = __expf(acc[mi][ni][hf * 2 + 1] - EXP_SHIFT);
                    part += e0 + e1;
                    *(__half2*)(st + rl * 136 + cl) =
                        __halves2half2(__float2half(e0), __float2half(e1));
                }
                rs[rl * 8 + slot] = part;
            }
        __syncthreads();
        // coalesced store: 128 rows x 256B
        const int r = tid >> 1, hh = tid & 1;
        uint4* dst = (uint4*)((__half*)Cout + (size_t)(aRow + r) * 2048 + bRow + hh * 64);
        const uint4* src = (const uint4*)(st + r * 136 + hh * 64);
#pragma unroll
        for (int j = 0; j < 8; j++) dst[j] = src[j];
        // partial sums (order unchanged vs previous rounds)
        if (tid < 128) {
            float s = 0.0f;
#pragma unroll
            for (int j = 0; j < 8; j++) s += rs[tid * 8 + j];
            aux[(size_t)(aRow + tid) * 16 + blockIdx.x] = s;
        }
    } else if (MODE == 2) {
        // fp16 * alpha: stage tile in smem, coalesced store (ld 768)
        __syncthreads();
        __half* st = (__half*)smem;                            // [128][136]
#pragma unroll
        for (int mi = 0; mi < 2; mi++)
#pragma unroll
            for (int hf = 0; hf < 2; hf++) {
                const int rl = wm * 32 + mi * 16 + g + hf * 8;
#pragma unroll
                for (int ni = 0; ni < 8; ni++) {
                    const int cl = wn * 64 + ni * 8 + q;
                    *(__half2*)(st + rl * 136 + cl) =
                        __halves2half2(__float2half(acc[mi][ni][hf * 2 + 0] * alpha),
                                       __float2half(acc[mi][ni][hf * 2 + 1] * alpha));
                }
            }
        __syncthreads();
        const int r = tid >> 1, hh = tid & 1;
        uint4* dst = (uint4*)((__half*)Cout + (size_t)(aRow + r) * DM + blockIdx.x * BN + hh * 64);
        const uint4* src = (const uint4*)(st + r * 136 + hh * 64);
#pragma unroll
        for (int j = 0; j < 8; j++) dst[j] = src[j];
    } else {   // MODE 6
#pragma unroll
        for (int mi = 0; mi < 2; mi++) {
#pragma unroll
            for (int hf = 0; hf < 2; hf++) {
                const int m = aRow + wm * 32 + mi * 16 + g + hf * 8;
                const float scale = 1.0f / aux[m];
#pragma unroll
                for (int ni = 0; ni < 8; ni++) {
                    const int cn = blockIdx.x * BN + wn * 64 + ni * 8 + q;
                    float2* C = (float2*)((float*)Cout + (size_t)m * 768 + cn);
                    *C = make_float2(acc[mi][ni][hf * 2 + 0] * scale,
                                     acc[mi][ni][hf * 2 + 1] * scale);
                }
            }
        }
    }
#undef ISSUE_STAGE
}

// ---------------------------------------------------------------------------
// Conversions
// ---------------------------------------------------------------------------
__global__ void __launch_bounds__(256) conv_X(const float* __restrict__ X, __half* __restrict__ Xh)
{
    size_t i = ((size_t)blockIdx.x * 256 + threadIdx.x) * 4;
    if (i >= (size_t)16384 * 768) return;
    float4 v = *(const float4*)(X + i);
    __half* o = Xh + i;
    *(__half2*)(o)     = __halves2half2(__float2half(v.x), __float2half(v.y));
    *(__half2*)(o + 2) = __halves2half2(__float2half(v.z), __float2half(v.w));
}

// W[k][e] -> Wt[e][k] fp16 (coalesced 32x32 smem transpose)
__global__ void __launch_bounds__(256) conv_Wt(const float* __restrict__ W, __half* __restrict__ Wh)
{
    __shared__ float tile[32][33];
    const int k0 = blockIdx.y * 32, e0 = blockIdx.x * 32;
    const int tx = threadIdx.x & 31, ty = threadIdx.x >> 5;
#pragma unroll
    for (int r = ty; r < 32; r += 8)
        tile[r][tx] = W[(size_t)(k0 + r) * 768 + e0 + tx];
    __syncthreads();
#pragma unroll
    for (int r = ty; r < 32; r += 8)
        Wh[(size_t)(e0 + r) * 768 + k0 + tx] = __float2half(tile[tx][r]);
}

// Sum 16 partials per row (deterministic fixed order)
__global__ void __launch_bounds__(256) rowsum(const float* __restrict__ part, float* __restrict__ sum)
{
    const int row = blockIdx.x * 256 + threadIdx.x;   // 0..2047
    float s = 0.0f;
#pragma unroll
    for (int j = 0; j < 16; j++) s += part[(size_t)row * 16 + j];
    sum[row] = s;
}

// ---------------------------------------------------------------------------
// Streams/events: created at static-init; reused deterministically.
// ---------------------------------------------------------------------------
struct StreamCtx {
    cudaStream_t st[BATCH];
    cudaEvent_t evRoot, evX, evWq, evWk, evWv, evDone[BATCH];
    StreamCtx() {
        for (int i = 0; i < BATCH; i++)
            cudaStreamCreateWithFlags(&st[i], cudaStreamNonBlocking);
        cudaEventCreateWithFlags(&evRoot, cudaEventDisableTiming);
        cudaEventCreateWithFlags(&evX, cudaEventDisableTiming);
        cudaEventCreateWithFlags(&evWq, cudaEventDisableTiming);
        cudaEventCreateWithFlags(&evWk, cudaEventDisableTiming);
        cudaEventCreateWithFlags(&evWv, cudaEventDisableTiming);
        for (int i = 0; i < BATCH; i++)
            cudaEventCreateWithFlags(&evDone[i], cudaEventDisableTiming);
    }
};
static StreamCtx g_sc;

// ---------------------------------------------------------------------------
// Launch: 8 independent per-batch chains, fused softmax
// ---------------------------------------------------------------------------
extern "C" void kernel_launch(void* const* d_in, const int* in_sizes, int n_in,
                              void* d_out, int out_size)
{
    const float* X  = (const float*)d_in[0];
    const float* Wq = (const float*)d_in[1];
    const float* Wk = (const float*)d_in[2];
    const float* Wv = (const float*)d_in[3];
    float* out = (float*)d_out;

    void *Xh_, *WqT_, *WkT_, *WvT_, *Qh_, *Kh_, *VT_, *Ph_, *Part_, *Sum_;
    cudaGetSymbolAddress(&Xh_, g_Xh);   cudaGetSymbolAddress(&WqT_, g_WqT);
    cudaGetSymbolAddress(&WkT_, g_WkT); cudaGetSymbolAddress(&WvT_, g_WvT);
    cudaGetSymbolAddress(&Qh_, g_Qh);   cudaGetSymbolAddress(&Kh_, g_Kh);
    cudaGetSymbolAddress(&VT_, g_VT);   cudaGetSymbolAddress(&Ph_, g_Ph);
    cudaGetSymbolAddress(&Part_, g_Part); cudaGetSymbolAddress(&Sum_, g_Sum);
    __half *Xh = (__half*)Xh_, *WqT = (__half*)WqT_, *WkT = (__half*)WkT_, *WvT = (__half*)WvT_;
    __half *Qh = (__half*)Qh_, *Kh = (__half*)Kh_, *VT = (__half*)VT_, *Ph = (__half*)Ph_;
    float *Part = (float*)Part_, *Sum = (float*)Sum_;

    static bool attr_done = false;
    if (!attr_done) {
        cudaFuncSetAttribute(gemm_mma<2>, cudaFuncAttributeMaxDynamicSharedMemorySize, SMEM_TOTAL);
        cudaFuncSetAttribute(gemm_mma<4>, cudaFuncAttributeMaxDynamicSharedMemorySize, SMEM_TOTAL);
        cudaFuncSetAttribute(gemm_mma<5>, cudaFuncAttributeMaxDynamicSharedMemorySize, SMEM_TOTAL);
        cudaFuncSetAttribute(gemm_mma<6>, cudaFuncAttributeMaxDynamicSharedMemorySize, SMEM_TOTAL);
        attr_done = true;
    }

    const float inv_sqrt_d = 1.0f / sqrtf((float)DM);
    StreamCtx& C = g_sc;

    cudaEventRecord(C.evRoot, 0);

    // 1) conversions in parallel on 4 streams
    cudaStreamWaitEvent(C.st[0], C.evRoot, 0);
    conv_X<<<(16384 * 768 / 4 + 255) / 256, 256, 0, C.st[0]>>>(X, Xh);
    cudaEventRecord(C.evX, C.st[0]);

    cudaStreamWaitEvent(C.st[1], C.evRoot, 0);
    conv_Wt<<<dim3(24, 24), 256, 0, C.st[1]>>>(Wq, WqT);
    cudaEventRecord(C.evWq, C.st[1]);

    cudaStreamWaitEvent(C.st[2], C.evRoot, 0);
    conv_Wt<<<dim3(24, 24), 256, 0, C.st[2]>>>(Wk, WkT);
    cudaEventRecord(C.evWk, C.st[2]);

    cudaStreamWaitEvent(C.st[3], C.evRoot, 0);
    conv_Wt<<<dim3(24, 24), 256, 0, C.st[3]>>>(Wv, WvT);
    cudaEventRecord(C.evWv, C.st[3]);

    // 2) 8 independent per-batch chains
    dim3 gp(768 / BN, SEQ / BM, 1);
    dim3 gs(SEQ / BN, SEQ / BM, 1);
    dim3 go(768 / BN, SEQ / BM, 1);

    for (int b = 0; b < BATCH; b++) {
        cudaStream_t s = C.st[b];
        const size_t x_off = (size_t)b * SEQ * DM;
        const size_t p_off = (size_t)b * SEQ * SEQ;
        __half* VTb = VT + (size_t)b * DM * SEQ;
        float* Partb = Part + (size_t)b * SEQ * 16;
        float* Sumb  = Sum + (size_t)b * SEQ;

        cudaStreamWaitEvent(s, C.evX, 0);
        cudaStreamWaitEvent(s, C.evWq, 0);
        cudaStreamWaitEvent(s, C.evWk, 0);
        cudaStreamWaitEvent(s, C.evWv, 0);

        gemm_mma<2><<<gp, 256, SMEM_TOTAL, s>>>(Xh + x_off, WqT, Qh + x_off, nullptr, DM / BK, DM, DM, inv_sqrt_d);
        gemm_mma<2><<<gp, 256, SMEM_TOTAL, s>>>(Xh + x_off, WkT, Kh + x_off, nullptr, DM / BK, DM, DM, 1.0f);
        gemm_mma<4><<<gp, 256, SMEM_TOTAL, s>>>(Xh + x_off, WvT, VTb, nullptr, DM / BK, DM, DM, 1.0f);

        // QK + fused exp + partial sums
        gemm_mma<5><<<gs, 256, SMEM_TOTAL, s>>>(Qh + x_off, Kh + x_off, Ph + p_off, Partb, DM / BK, DM, DM, 1.0f);
        rowsum<<<SEQ / 256, 256, 0, s>>>(Partb, Sumb);
        // PV + fused normalization
        gemm_mma<6><<<go, 256, SMEM_TOTAL, s>>>(Ph + p_off, VTb, out + x_off, Sumb, SEQ / BK, SEQ, SEQ, 1.0f);

        cudaEventRecord(C.evDone[b], s);
    }

    // 3) join
    for (int b = 0; b < BATCH; b++)
        cudaStreamWaitEvent((cudaStream_t)0, C.evDone[b], 0);
}

// round 17
// speedup vs baseline: 1.0242x; 1.0242x over previous
#include <cuda_runtime.h>
#include <cuda_fp16.h>
#include <math.h>
#include <stdint.h>

#define BATCH 8
#define SEQ   2048
#define DM    768

// GEMM tiling
#define BM 128
#define BN 128
#define BK 64                       // 64 fp16 = 128 bytes per smem row
#define NSTAGE 3
#define A_TILE_BYTES (BM * 128)
#define B_TILE_BYTES (BN * 128)
#define STAGE_BYTES  (A_TILE_BYTES + B_TILE_BYTES)       // 32768
#define SMEM_TOTAL   (NSTAGE * STAGE_BYTES)              // 98304 -> 2 CTAs/SM

#define EXP_SHIFT 8.0f              // fixed softmax shift (cancels in normalization)

// ---------------------------------------------------------------------------
// Static device scratch
// ---------------------------------------------------------------------------
__device__ __align__(128) __half g_Xh [16384 * DM];           // fp16 X
__device__ __align__(128) __half g_WqT[DM * DM];              // fp16 Wq^T [e][k]
__device__ __align__(128) __half g_WkT[DM * DM];              // fp16 Wk^T
__device__ __align__(128) __half g_WvT[DM * DM];              // fp16 Wv^T
__device__ __align__(128) __half g_Qh [16384 * DM];           // fp16 Q/sqrt(d)
__device__ __align__(128) __half g_Kh [16384 * DM];           // fp16 K
__device__ __align__(128) __half g_VT [(BATCH * DM) * SEQ];   // fp16 V^T [b*768+e][s]
__device__ __align__(128) __half g_Ph [16384 * SEQ];          // fp16 unnormalized exp(s-8)
__device__ __align__(128) float  g_Part[16384 * 16];          // per-CTA row-sum partials
__device__ __align__(128) float  g_Sum [16384];               // row sums

// ---------------------------------------------------------------------------
// PTX helpers (baseline sm_100 ISA: cp.async, ldmatrix, mma.sync)
// ---------------------------------------------------------------------------
__device__ __forceinline__ uint32_t smem_u32(const void* p) {
    uint32_t a;
    asm("{ .reg .u64 t; cvta.to.shared.u64 t, %1; cvt.u32.u64 %0, t; }" : "=r"(a) : "l"(p));
    return a;
}
#define CP_ASYNC16(dst, src) \
    asm volatile("cp.async.cg.shared.global [%0], [%1], 16;" :: "r"(dst), "l"(src))
#define CP_COMMIT() asm volatile("cp.async.commit_group;" ::: "memory")
#define CP_WAIT1()  asm volatile("cp.async.wait_group 1;" ::: "memory")

__device__ __forceinline__ void ldsm_x4(uint32_t& r0, uint32_t& r1, uint32_t& r2, uint32_t& r3, uint32_t addr) {
    asm volatile("ldmatrix.sync.aligned.m8n8.x4.shared.b16 {%0,%1,%2,%3}, [%4];"
        : "=r"(r0), "=r"(r1), "=r"(r2), "=r"(r3) : "r"(addr));
}
__device__ __forceinline__ void mma_fp16(float* d, const uint32_t* a, const uint32_t* b) {
    asm volatile("mma.sync.aligned.m16n8k16.row.col.f32.f16.f16.f32 "
        "{%0,%1,%2,%3}, {%4,%5,%6,%7}, {%8,%9}, {%0,%1,%2,%3};"
        : "+f"(d[0]), "+f"(d[1]), "+f"(d[2]), "+f"(d[3])
        : "r"(a[0]), "r"(a[1]), "r"(a[2]), "r"(a[3]), "r"(b[0]), "r"(b[1]));
}

// ---------------------------------------------------------------------------
// NT GEMM via fp16 mma.sync: C[M,N] = A[M,:] . B[N,:]^T over K = NC*64.
// Modes:
//  2: fp16 *alpha -> C (ld 768)       [proj Q / proj K]
//  4: fp16 transposed COALESCED store -> V_T(batch) via smem tile [proj V]
//  5: __expf(s-8) -> fp16 Ph (ld 2048) + deterministic per-CTA row partials -> aux
//  6: fp32 * (1/aux[m]) -> C (ld 768) [PV -> out, fused normalization]
// ---------------------------------------------------------------------------
template <int MODE>
__global__ void __launch_bounds__(256, 2) gemm_mma(
    const __half* __restrict__ A, const __half* __restrict__ Bm,
    void* __restrict__ Cout, float* __restrict__ aux,
    int NC, int ldA, int ldB, float alpha)
{
    extern __shared__ __align__(1024) char smem[];
    const uint32_t sb = smem_u32(smem);
    const int tid = threadIdx.x;
    const int wid = tid >> 5, lid = tid & 31;
    const int wm = wid & 3, wn = wid >> 2;           // warp grid 4(m) x 2(n)

    const int aRow = blockIdx.y * BM;
    const int bRow = blockIdx.x * BN;
    const __half* gA0 = A  + (size_t)aRow * ldA;
    const __half* gB0 = Bm + (size_t)bRow * ldB;

    const int lr = tid >> 3, lc = tid & 7;

    float acc[2][8][4];
#pragma unroll
    for (int mi = 0; mi < 2; mi++)
#pragma unroll
        for (int ni = 0; ni < 8; ni++)
#pragma unroll
            for (int j = 0; j < 4; j++) acc[mi][ni][j] = 0.0f;

#define ISSUE_STAGE(chunk, stage) do { \
    uint32_t _sA = sb + (stage) * STAGE_BYTES; \
    uint32_t _sB = _sA + A_TILE_BYTES; \
    const __half* _gA = gA0 + (size_t)(chunk) * BK; \
    const __half* _gB = gB0 + (size_t)(chunk) * BK; \
    _Pragma("unroll") \
    for (int _j = 0; _j < 4; _j++) { \
        int _r = lr + _j * 32, _c = lc; \
        uint32_t _d = _r * 128 + ((_c ^ (_r & 7)) * 16); \
        CP_ASYNC16(_sA + _d, _gA + (size_t)_r * ldA + _c * 8); \
        CP_ASYNC16(_sB + _d, _gB + (size_t)_r * ldB + _c * 8); \
    } } while (0)

    for (int s = 0; s < 2; s++) {
        if (s < NC) ISSUE_STAGE(s, s);
        CP_COMMIT();
    }

    const int a_row = wm * 32 + (lid & 15);
    const int a_cSel = (lid >> 4);
    const int b_row = wn * 64 + (lid & 7) + ((lid >> 4) & 1) * 8;
    const int b_cSel = (lid >> 3) & 1;

    int stg = 0, stg2 = 2;
    for (int i = 0; i < NC; i++) {
        CP_WAIT1();
        __syncthreads();
        if (i + 2 < NC) ISSUE_STAGE(i + 2, stg2);
        CP_COMMIT();

        const uint32_t aBase = sb + stg * STAGE_BYTES;
        const uint32_t bBase = aBase + A_TILE_BYTES;
        stg2 = stg;
        stg = (stg + 1 == NSTAGE) ? 0 : stg + 1;
#pragma unroll
        for (int kk = 0; kk < 4; kk++) {
            uint32_t a[2][4], b[8][2];
#pragma unroll
            for (int mi = 0; mi < 2; mi++) {
                int row = a_row + mi * 16;
                int c = kk * 2 + a_cSel;
                ldsm_x4(a[mi][0], a[mi][1], a[mi][2], a[mi][3],
                        aBase + row * 128 + ((c ^ (row & 7)) * 16));
            }
#pragma unroll
            for (int nt = 0; nt < 4; nt++) {
                int row = b_row + nt * 16;
                int c = kk * 2 + b_cSel;
                ldsm_x4(b[2 * nt][0], b[2 * nt][1], b[2 * nt + 1][0], b[2 * nt + 1][1],
                        bBase + row * 128 + ((c ^ (row & 7)) * 16));
            }
#pragma unroll
            for (int mi = 0; mi < 2; mi++)
#pragma unroll
                for (int ni = 0; ni < 8; ni++)
                    mma_fp16(acc[mi][ni], a[mi], b[ni]);
        }
    }

    // ---- epilogue ----
    const int g = lid >> 2, q = (lid & 3) * 2;

    if (MODE == 4) {
        // stage transposed tile [e_local][s_local] in smem, then coalesced store
        __syncthreads();
        __half* st = (__half*)smem;                        // [128][136]
#pragma unroll
        for (int mi = 0; mi < 2; mi++)
#pragma unroll
            for (int hf = 0; hf < 2; hf++) {
                const int sl = wm * 32 + mi * 16 + g + hf * 8;
#pragma unroll
                for (int ni = 0; ni < 8; ni++) {
                    const int el = wn * 64 + ni * 8 + q;
                    st[el * 136 + sl]       = __float2half(acc[mi][ni][hf * 2 + 0]);
                    st[(el + 1) * 136 + sl] = __float2half(acc[mi][ni][hf * 2 + 1]);
                }
            }
        __syncthreads();
        const int s0 = aRow;
        const int r = tid >> 1, hh = tid & 1;
        const int eg = blockIdx.x * BN + r;
        uint4* dst = (uint4*)((__half*)Cout + (size_t)eg * 2048 + s0 + hh * 64);
        const uint4* src = (const uint4*)(st + r * 136 + hh * 64);
#pragma unroll
        for (int j = 0; j < 8; j++) dst[j] = src[j];
    } else if (MODE == 5) {
        // __expf(s - 8) -> fp16 Ph; deterministic row-sum partials -> aux
        __syncthreads();
        float* rs = (float*)smem;                          // [128][8]
        const int slot = wn * 4 + (lid & 3);
#pragma unroll
        for (int mi = 0; mi < 2; mi++)
#pragma unroll
            for (int hf = 0; hf < 2; hf++) {
                const int rl = wm * 32 + mi * 16 + g + hf * 8;
                const int m = aRow + rl;
                float part = 0.0f;
#pragma unroll
                for (int ni = 0; ni < 8; ni++) {
                    const int cn = bRow + wn * 64 + ni * 8 + q;
                    float e0 = __expf(acc[mi][ni][hf * 2 + 0] - EXP_SHIFT);
                    float e1 = __expf(acc[mi][ni][hf * 2 + 1] - EXP_SHIFT);
                    part += e0 + e1;
                    *(__half2*)((__half*)Cout + (size_t)m * 2048 + cn) =
                        __halves2half2(__float2half(e0), __float2half(e1));
                }
                rs[rl * 8 + slot] = part;
            }
        __syncthreads();
        if (tid < 128) {
            float s = 0.0f;
#pragma unroll
            for (int j = 0; j < 8; j++) s += rs[tid * 8 + j];
            aux[(size_t)(aRow + tid) * 16 + blockIdx.x] = s;
        }
    } else {
#pragma unroll
        for (int mi = 0; mi < 2; mi++) {
#pragma unroll
            for (int hf = 0; hf < 2; hf++) {
                const int m = aRow + wm * 32 + mi * 16 + g + hf * 8;
                float scale = alpha;
                if (MODE == 6) scale = 1.0f / aux[m];
#pragma unroll
                for (int ni = 0; ni < 8; ni++) {
                    const int cn = blockIdx.x * BN + wn * 64 + ni * 8 + q;
                    const float v0 = acc[mi][ni][hf * 2 + 0];
                    const float v1 = acc[mi][ni][hf * 2 + 1];
                    if (MODE == 6) {
                        float2* C = (float2*)((float*)Cout + (size_t)m * 768 + cn);
                        *C = make_float2(v0 * scale, v1 * scale);
                    } else {   // MODE 2: fp16 * alpha, ld 768
                        __half* C = (__half*)Cout + (size_t)m * DM;
                        *(__half2*)(C + cn) = __halves2half2(__float2half(v0 * scale),
                                                             __float2half(v1 * scale));
                    }
                }
            }
        }
    }
#undef ISSUE_STAGE
}

// ---------------------------------------------------------------------------
// Conversions
// ---------------------------------------------------------------------------
// per-batch slice of X (2048 rows): grid covers SEQ*DM/4 elements
__global__ void __launch_bounds__(256) conv_X(const float* __restrict__ X, __half* __restrict__ Xh)
{
    size_t i = ((size_t)blockIdx.x * 256 + threadIdx.x) * 4;
    if (i >= (size_t)SEQ * DM) return;
    float4 v = *(const float4*)(X + i);
    __half* o = Xh + i;
    *(__half2*)(o)     = __halves2half2(__float2half(v.x), __float2half(v.y));
    *(__half2*)(o + 2) = __halves2half2(__float2half(v.z), __float2half(v.w));
}

// W[k][e] -> Wt[e][k] fp16 (coalesced 32x32 smem transpose)
__global__ void __launch_bounds__(256) conv_Wt(const float* __restrict__ W, __half* __restrict__ Wh)
{
    __shared__ float tile[32][33];
    const int k0 = blockIdx.y * 32, e0 = blockIdx.x * 32;
    const int tx = threadIdx.x & 31, ty = threadIdx.x >> 5;
#pragma unroll
    for (int r = ty; r < 32; r += 8)
        tile[r][tx] = W[(size_t)(k0 + r) * 768 + e0 + tx];
    __syncthreads();
#pragma unroll
    for (int r = ty; r < 32; r += 8)
        Wh[(size_t)(e0 + r) * 768 + k0 + tx] = __float2half(tile[tx][r]);
}

// Sum 16 partials per row (deterministic fixed order)
__global__ void __launch_bounds__(256) rowsum(const float* __restrict__ part, float* __restrict__ sum)
{
    const int row = blockIdx.x * 256 + threadIdx.x;   // 0..2047
    float s = 0.0f;
#pragma unroll
    for (int j = 0; j < 16; j++) s += part[(size_t)row * 16 + j];
    sum[row] = s;
}

// ---------------------------------------------------------------------------
// Streams/events: created at static-init; reused deterministically.
// ---------------------------------------------------------------------------
struct StreamCtx {
    cudaStream_t st[BATCH];
    cudaEvent_t evRoot, evWq, evWk, evWv, evDone[BATCH];
    StreamCtx() {
        for (int i = 0; i < BATCH; i++)
            cudaStreamCreateWithFlags(&st[i], cudaStreamNonBlocking);
        cudaEventCreateWithFlags(&evRoot, cudaEventDisableTiming);
        cudaEventCreateWithFlags(&evWq, cudaEventDisableTiming);
        cudaEventCreateWithFlags(&evWk, cudaEventDisableTiming);
        cudaEventCreateWithFlags(&evWv, cudaEventDisableTiming);
        for (int i = 0; i < BATCH; i++)
            cudaEventCreateWithFlags(&evDone[i], cudaEventDisableTiming);
    }
};
static StreamCtx g_sc;

// ---------------------------------------------------------------------------
// Launch: 8 independent per-batch chains; per-batch X conversion in-stream
// ---------------------------------------------------------------------------
extern "C" void kernel_launch(void* const* d_in, const int* in_sizes, int n_in,
                              void* d_out, int out_size)
{
    const float* X  = (const float*)d_in[0];
    const float* Wq = (const float*)d_in[1];
    const float* Wk = (const float*)d_in[2];
    const float* Wv = (const float*)d_in[3];
    float* out = (float*)d_out;

    void *Xh_, *WqT_, *WkT_, *WvT_, *Qh_, *Kh_, *VT_, *Ph_, *Part_, *Sum_;
    cudaGetSymbolAddress(&Xh_, g_Xh);   cudaGetSymbolAddress(&WqT_, g_WqT);
    cudaGetSymbolAddress(&WkT_, g_WkT); cudaGetSymbolAddress(&WvT_, g_WvT);
    cudaGetSymbolAddress(&Qh_, g_Qh);   cudaGetSymbolAddress(&Kh_, g_Kh);
    cudaGetSymbolAddress(&VT_, g_VT);   cudaGetSymbolAddress(&Ph_, g_Ph);
    cudaGetSymbolAddress(&Part_, g_Part); cudaGetSymbolAddress(&Sum_, g_Sum);
    __half *Xh = (__half*)Xh_, *WqT = (__half*)WqT_, *WkT = (__half*)WkT_, *WvT = (__half*)WvT_;
    __half *Qh = (__half*)Qh_, *Kh = (__half*)Kh_, *VT = (__half*)VT_, *Ph = (__half*)Ph_;
    float *Part = (float*)Part_, *Sum = (float*)Sum_;

    static bool attr_done = false;
    if (!attr_done) {
        cudaFuncSetAttribute(gemm_mma<2>, cudaFuncAttributeMaxDynamicSharedMemorySize, SMEM_TOTAL);
        cudaFuncSetAttribute(gemm_mma<4>, cudaFuncAttributeMaxDynamicSharedMemorySize, SMEM_TOTAL);
        cudaFuncSetAttribute(gemm_mma<5>, cudaFuncAttributeMaxDynamicSharedMemorySize, SMEM_TOTAL);
        cudaFuncSetAttribute(gemm_mma<6>, cudaFuncAttributeMaxDynamicSharedMemorySize, SMEM_TOTAL);
        attr_done = true;
    }

    const float inv_sqrt_d = 1.0f / sqrtf((float)DM);
    StreamCtx& C = g_sc;

    cudaEventRecord(C.evRoot, 0);

    // 1) weight conversions on streams 1-3 (shared across batches)
    cudaStreamWaitEvent(C.st[1], C.evRoot, 0);
    conv_Wt<<<dim3(24, 24), 256, 0, C.st[1]>>>(Wq, WqT);
    cudaEventRecord(C.evWq, C.st[1]);

    cudaStreamWaitEvent(C.st[2], C.evRoot, 0);
    conv_Wt<<<dim3(24, 24), 256, 0, C.st[2]>>>(Wk, WkT);
    cudaEventRecord(C.evWk, C.st[2]);

    cudaStreamWaitEvent(C.st[3], C.evRoot, 0);
    conv_Wt<<<dim3(24, 24), 256, 0, C.st[3]>>>(Wv, WvT);
    cudaEventRecord(C.evWv, C.st[3]);

    // 2) 8 independent per-batch chains (X conversion in-stream, per batch)
    dim3 gp(768 / BN, SEQ / BM, 1);
    dim3 gs(SEQ / BN, SEQ / BM, 1);
    dim3 go(768 / BN, SEQ / BM, 1);
    const int convx_blocks = (SEQ * DM / 4 + 255) / 256;

    for (int b = 0; b < BATCH; b++) {
        cudaStream_t s = C.st[b];
        const size_t x_off = (size_t)b * SEQ * DM;
        const size_t p_off = (size_t)b * SEQ * SEQ;
        __half* VTb = VT + (size_t)b * DM * SEQ;
        float* Partb = Part + (size_t)b * SEQ * 16;
        float* Sumb  = Sum + (size_t)b * SEQ;

        cudaStreamWaitEvent(s, C.evRoot, 0);
        // per-batch X slice conversion (no cross-stream barrier needed)
        conv_X<<<convx_blocks, 256, 0, s>>>(X + x_off, Xh + x_off);

        cudaStreamWaitEvent(s, C.evWq, 0);
        cudaStreamWaitEvent(s, C.evWk, 0);
        cudaStreamWaitEvent(s, C.evWv, 0);

        gemm_mma<2><<<gp, 256, SMEM_TOTAL, s>>>(Xh + x_off, WqT, Qh + x_off, nullptr, DM / BK, DM, DM, inv_sqrt_d);
        gemm_mma<2><<<gp, 256, SMEM_TOTAL, s>>>(Xh + x_off, WkT, Kh + x_off, nullptr, DM / BK, DM, DM, 1.0f);
        gemm_mma<4><<<gp, 256, SMEM_TOTAL, s>>>(Xh + x_off, WvT, VTb, nullptr, DM / BK, DM, DM, 1.0f);

        // QK + fused exp + partial sums
        gemm_mma<5><<<gs, 256, SMEM_TOTAL, s>>>(Qh + x_off, Kh + x_off, Ph + p_off, Partb, DM / BK, DM, DM, 1.0f);
        rowsum<<<SEQ / 256, 256, 0, s>>>(Partb, Sumb);
        // PV + fused normalization
        gemm_mma<6><<<go, 256, SMEM_TOTAL, s>>>(Ph + p_off, VTb, out + x_off, Sumb, SEQ / BK, SEQ, SEQ, 1.0f);

        cudaEventRecord(C.evDone[b], s);
    }

    // 3) join
    for (int b = 0; b < BATCH; b++)
        cudaStreamWaitEvent((cudaStream_t)0, C.evDone[b], 0);
}